// round 1
// baseline (speedup 1.0000x reference)
#include <cuda_runtime.h>
#include <math.h>

// Problem constants (fixed by the reference)
#define TT 512
#define NN 256
#define CC 256
#define SS 48
#define LL 97           // 2*S+1 extended lattice
#define NEGV (-1e30f)

// Scratch for per-batch losses (no allocation allowed -> device global)
__device__ float g_loss_n[NN];

__device__ __forceinline__ float lae(float a, float b) {
    // logaddexp, safe for both args == NEGV
    float m = fmaxf(a, b);
    float d = fminf(a, b) - m;       // <= 0
    return m + log1pf(__expf(d));
}

__global__ __launch_bounds__(128, 2)
void ctc_alpha_kernel(const float* __restrict__ logits,
                      const int*   __restrict__ labels,
                      const int*   __restrict__ pred_sizes,
                      const int*   __restrict__ tgt_sizes)
{
    const int n   = blockIdx.x;
    const int tid = threadIdx.x;

    __shared__ float row[2][CC];        // double-buffered emission row
    __shared__ float abuf[2][LL + 2];   // alpha, padded with 2 NEG at front

    const float* lp_n = logits + (size_t)n * CC;   // + t*NN*CC for time t

    // Per-thread extended label + skip flag (thread l <-> lattice state l)
    int  ext  = 0;
    bool skip = false;
    if (tid < LL) {
        if (tid & 1) {
            int s = tid >> 1;
            ext = labels[n * SS + s];
            int prev2 = (tid >= 3) ? labels[n * SS + s - 1] : 0;
            skip = (ext != 0) && (ext != prev2);
        }
    }
    const int in_len = pred_sizes[n];

    // Pad entries (indices 0,1) stay NEG forever in both buffers
    if (tid < 2) { abuf[0][tid] = NEGV; abuf[1][tid] = NEGV; }

    // alpha at t=0
    if (tid < LL) {
        float a0 = NEGV;
        if (tid == 0)      a0 = __ldg(lp_n + 0);     // blank
        else if (tid == 1) a0 = __ldg(lp_n + ext);   // first label
        abuf[0][tid + 2] = a0;
    }

    // Preload emission row for t=1
    {
        const float2* src = (const float2*)(lp_n + (size_t)1 * NN * CC);
        ((float2*)row[0])[tid] = src[tid];
    }
    __syncthreads();

    #pragma unroll 1
    for (int t = 1; t < TT; t++) {
        const int cur = (t - 1) & 1;
        const int nxt = t & 1;

        // Issue next-row global load EARLY (hides DRAM latency behind compute)
        float2 r;
        const bool do_pref = (t + 1 < TT);
        if (do_pref) {
            const float2* src = (const float2*)(lp_n + (size_t)(t + 1) * NN * CC);
            r = src[tid];
        }

        float newa = NEGV;
        if (tid < LL) {
            float a  = abuf[cur][tid + 2];
            float s1 = abuf[cur][tid + 1];
            float c  = lae(a, s1);
            if (skip) c = lae(c, abuf[cur][tid]);
            float v = c + row[cur][ext];
            newa = (t < in_len) ? v : a;
        }

        if (do_pref) ((float2*)row[nxt])[tid] = r;
        if (tid < LL) abuf[nxt][tid + 2] = newa;

        __syncthreads();
    }

    if (tid == 0) {
        const int fin = (TT - 1) & 1;
        int tl = tgt_sizes[n];
        float a1 = abuf[fin][2 + 2 * tl - 1];
        float a2 = abuf[fin][2 + 2 * tl];
        float loss = -lae(a1, a2);
        if (loss > 1e29f) loss = 0.0f;     // zero_infinity
        g_loss_n[n] = loss / (float)tl;
    }
}

__global__ __launch_bounds__(256)
void ctc_reduce_kernel(float* __restrict__ out)
{
    __shared__ float sh[256];
    int tid = threadIdx.x;
    float v = g_loss_n[tid];
    sh[tid] = v;
    __syncthreads();
    for (int off = 128; off > 0; off >>= 1) {
        if (tid < off) sh[tid] += sh[tid + off];
        __syncthreads();
    }
    if (tid == 0) {
        float m = sh[0] / (float)NN;
        if (isnan(m) || isinf(m)) m = 0.0f;
        out[0] = m;
    }
}

extern "C" void kernel_launch(void* const* d_in, const int* in_sizes, int n_in,
                              void* d_out, int out_size)
{
    const float* logits     = (const float*)d_in[0];
    const int*   labels     = (const int*)  d_in[1];
    const int*   pred_sizes = (const int*)  d_in[2];
    const int*   tgt_sizes  = (const int*)  d_in[3];
    float*       out        = (float*)d_out;

    ctc_alpha_kernel<<<NN, 128>>>(logits, labels, pred_sizes, tgt_sizes);
    ctc_reduce_kernel<<<1, 256>>>(out);
}

// round 2
// speedup vs baseline: 4.4600x; 4.4600x over previous
#include <cuda_runtime.h>
#include <math.h>
#include <stdint.h>

#define TT 512
#define NN 256
#define CC 256
#define SS 48
#define LL 97
#define NEGV (-1e30f)
#define LOG2E 1.4426950408889634f
#define LN2   0.6931471805599453f

#define ROWS 4                      // batch rows per CTA (one per warp/SMSP)
#define CHUNK 16                    // timesteps per ring buffer
#define NBUF 3
#define NCHUNK (TT / CHUNK)         // 32
#define GRID (NN / ROWS)            // 64
#define TILE_FLOATS (ROWS * CC)     // 1024 floats = 4KB per timestep
#define BUF_FLOATS (CHUNK * TILE_FLOATS)
#define SMEM_BYTES (NBUF * BUF_FLOATS * 4)  // 196608 B

__device__ float g_loss_n[NN];
__device__ int   g_count;           // zero-init; self-resetting per launch

__device__ __forceinline__ uint32_t s2u(const void* p) {
    return (uint32_t)__cvta_generic_to_shared(p);
}
__device__ __forceinline__ float ex2f(float x) {
    float y; asm("ex2.approx.ftz.f32 %0, %1;" : "=f"(y) : "f"(x)); return y;
}
__device__ __forceinline__ float lg2f(float x) {
    float y; asm("lg2.approx.ftz.f32 %0, %1;" : "=f"(y) : "f"(x)); return y;
}

// log2-domain logaddexp (2-way)
__device__ __forceinline__ float comb2(float x0, float x1) {
    float m = fmaxf(x0, x1);
    float d = fminf(x0, x1) - m;                 // <= 0
    return m + lg2f(1.0f + ex2f(d));
}
// log2-domain logaddexp (3-way, third term gated by u)
__device__ __forceinline__ float comb3(float x0, float x1, float x2, bool u) {
    float hi = fmaxf(x0, x1), lo = fminf(x0, x1);
    float x2e = u ? x2 : NEGV;
    float m = fmaxf(hi, x2e);
    float s = 1.0f + ex2f(fminf(hi, x2e) - m) + ex2f(lo - m);
    return m + lg2f(s);
}

__device__ __forceinline__ void mbar_wait(uint32_t addr, uint32_t parity) {
    asm volatile(
        "{\n"
        ".reg .pred P;\n"
        "WL%=:\n"
        "mbarrier.try_wait.parity.acquire.cta.shared::cta.b64 P, [%0], %1, 0x989680;\n"
        "@P bra WD%=;\n"
        "bra WL%=;\n"
        "WD%=:\n"
        "}\n" :: "r"(addr), "r"(parity) : "memory");
}

// one alpha-recursion step; uses scope vars: lane, lab_a, lab_b, sk1, sk3, in_len, a0..a3
#define STEP(rp, t) do {                                                        \
    float lpb = (rp)[0];                                                        \
    float lpa = (rp)[lab_a];                                                    \
    float lpc = (rp)[lab_b];                                                    \
    float p3 = __shfl_up_sync(0xffffffffu, a3, 1);                              \
    if (lane == 0) p3 = NEGV;                                                   \
    float n0 = comb2(a0, p3);              /* even state: no skip */            \
    float n1 = comb3(a1, a0, p3, sk1);                                          \
    float n2 = comb2(a2, a1);                                                   \
    float n3 = comb3(a3, a2, a1, sk3);                                          \
    n0 = fmaf(lpb, LOG2E, n0);                                                  \
    n1 = fmaf(lpa, LOG2E, n1);                                                  \
    n2 = fmaf(lpb, LOG2E, n2);                                                  \
    n3 = fmaf(lpc, LOG2E, n3);                                                  \
    bool act = (t) < in_len;                                                    \
    a0 = act ? n0 : a0;  a1 = act ? n1 : a1;                                    \
    a2 = act ? n2 : a2;  a3 = act ? n3 : a3;                                    \
} while (0)

__global__ __launch_bounds__(128, 1)
void ctc_kernel(const float* __restrict__ logits,
                const int*   __restrict__ labels,
                const int*   __restrict__ pred_sizes,
                const int*   __restrict__ tgt_sizes,
                float*       __restrict__ out)
{
    extern __shared__ float tiles[];
    __shared__ __align__(8) unsigned long long mb_full[NBUF];
    __shared__ __align__(8) unsigned long long mb_empty[NBUF];
    __shared__ float red[4];
    __shared__ int s_last;

    const int tid  = threadIdx.x;
    const int wid  = tid >> 5;
    const int lane = tid & 31;
    const int n    = blockIdx.x * ROWS + wid;

    // per-lane extended labels + skip flags (lane k owns states 4k..4k+3)
    const int k = lane;
    int lab_a = (2 * k     < SS) ? labels[n * SS + 2 * k]     : 0;  // state 4k+1
    int lab_b = (2 * k + 1 < SS) ? labels[n * SS + 2 * k + 1] : 0;  // state 4k+3
    int lab_p = (2 * k - 1 >= 0) ? labels[n * SS + 2 * k - 1] : 0;
    bool sk1 = (lab_a != 0) && (lab_a != lab_p);
    bool sk3 = (lab_b != 0) && (lab_b != lab_a);
    const int in_len = pred_sizes[n];

    if (tid == 0) {
        #pragma unroll
        for (int b = 0; b < NBUF; b++) {
            asm volatile("mbarrier.init.shared.b64 [%0], %1;" :: "r"(s2u(&mb_full[b])),  "r"(1));
            asm volatile("mbarrier.init.shared.b64 [%0], %1;" :: "r"(s2u(&mb_empty[b])), "r"(ROWS));
        }
        asm volatile("fence.proxy.async.shared::cta;" ::: "memory");
    }
    __syncthreads();

    const float* src_base = logits + (size_t)blockIdx.x * ROWS * CC;  // + t*NN*CC

    // prologue: fill all NBUF buffers (chunks 0..NBUF-1); buffers start empty
    if (tid == 0) {
        #pragma unroll
        for (int c = 0; c < NBUF; c++) {
            uint32_t f = s2u(&mb_full[c]);
            asm volatile("mbarrier.arrive.expect_tx.shared.b64 _, [%0], %1;"
                         :: "r"(f), "r"(BUF_FLOATS * 4) : "memory");
            for (int j = 0; j < CHUNK; j++) {
                int t = c * CHUNK + j;
                uint32_t dst = s2u(&tiles[(c * CHUNK + j) * TILE_FLOATS]);
                const float* src = src_base + (size_t)t * NN * CC;
                asm volatile("cp.async.bulk.shared::cluster.global.mbarrier::complete_tx::bytes "
                             "[%0], [%1], %2, [%3];"
                             :: "r"(dst), "l"(src), "r"(TILE_FLOATS * 4), "r"(f) : "memory");
            }
        }
    }

    float a0 = NEGV, a1 = NEGV, a2 = NEGV, a3 = NEGV;

    for (int c = 0; c < NCHUNK; c++) {
        const int b = c % NBUF;
        mbar_wait(s2u(&mb_full[b]), (c / NBUF) & 1);

        #pragma unroll
        for (int j = 0; j < CHUNK; j++) {
            const int t = c * CHUNK + j;
            const float* rp = &tiles[(b * CHUNK + j) * TILE_FLOATS + wid * CC];
            if (t == 0) {
                if (lane == 0) { a0 = rp[0] * LOG2E; a1 = rp[lab_a] * LOG2E; }
            } else {
                STEP(rp, t);
            }
        }

        if (lane == 0)
            asm volatile("mbarrier.arrive.shared.b64 _, [%0];"
                         :: "r"(s2u(&mb_empty[b])) : "memory");

        // producer refills this buffer with chunk c+NBUF once all warps released it
        if (tid == 0 && c + NBUF < NCHUNK) {
            const int cn = c + NBUF;
            mbar_wait(s2u(&mb_empty[b]), (cn / NBUF + 1) & 1);  // ((cn/NBUF)-1)&1
            uint32_t f = s2u(&mb_full[b]);
            asm volatile("mbarrier.arrive.expect_tx.shared.b64 _, [%0], %1;"
                         :: "r"(f), "r"(BUF_FLOATS * 4) : "memory");
            for (int j = 0; j < CHUNK; j++) {
                int t = cn * CHUNK + j;
                uint32_t dst = s2u(&tiles[(b * CHUNK + j) * TILE_FLOATS]);
                const float* src = src_base + (size_t)t * NN * CC;
                asm volatile("cp.async.bulk.shared::cluster.global.mbarrier::complete_tx::bytes "
                             "[%0], [%1], %2, [%3];"
                             :: "r"(dst), "l"(src), "r"(TILE_FLOATS * 4), "r"(f) : "memory");
            }
        }
    }

    // per-row loss (log2 domain -> natural log)
    {
        int tl = tgt_sizes[n];
        int i1 = 2 * tl - 1, i2 = 2 * tl;            // tl>=1
        int sel1 = i1 & 3, sl1 = i1 >> 2;
        float x1 = (sel1 == 0) ? a0 : (sel1 == 1) ? a1 : (sel1 == 2) ? a2 : a3;
        x1 = __shfl_sync(0xffffffffu, x1, sl1);
        int sel2 = i2 & 3, sl2 = i2 >> 2;
        float x2 = (sel2 == 0) ? a0 : (sel2 == 1) ? a1 : (sel2 == 2) ? a2 : a3;
        x2 = __shfl_sync(0xffffffffu, x2, sl2);
        float loss = -LN2 * comb2(x1, x2);
        if (loss > 1e29f) loss = 0.0f;               // zero_infinity
        if (lane == 0) g_loss_n[n] = loss / (float)tl;
    }

    // fused mean-reduction: last CTA to finish does it
    __syncthreads();
    if (tid == 0) {
        __threadfence();
        int old = atomicAdd(&g_count, 1);
        s_last = (old == (int)gridDim.x - 1) ? 1 : 0;
    }
    __syncthreads();
    if (s_last) {
        __threadfence();
        float v = __ldcg(&g_loss_n[tid]) + __ldcg(&g_loss_n[tid + 128]);
        #pragma unroll
        for (int o = 16; o; o >>= 1) v += __shfl_down_sync(0xffffffffu, v, o);
        if (lane == 0) red[wid] = v;
        __syncthreads();
        if (tid == 0) {
            float m = (red[0] + red[1] + red[2] + red[3]) / (float)NN;
            if (isnan(m) || isinf(m)) m = 0.0f;
            out[0] = m;
            g_count = 0;   // reset for next graph replay
        }
    }
}

extern "C" void kernel_launch(void* const* d_in, const int* in_sizes, int n_in,
                              void* d_out, int out_size)
{
    const float* logits     = (const float*)d_in[0];
    const int*   labels     = (const int*)  d_in[1];
    const int*   pred_sizes = (const int*)  d_in[2];
    const int*   tgt_sizes  = (const int*)  d_in[3];
    float*       out        = (float*)d_out;

    cudaFuncSetAttribute(ctc_kernel, cudaFuncAttributeMaxDynamicSharedMemorySize, SMEM_BYTES);
    ctc_kernel<<<GRID, 128, SMEM_BYTES>>>(logits, labels, pred_sizes, tgt_sizes, out);
}